// round 13
// baseline (speedup 1.0000x reference)
#include <cuda_runtime.h>
#include <cuda_fp16.h>
#include <cstdint>

// Conv2d 3x3 (B=32,Cin=128,56x56 -> Cout=256, pad 1) as implicit GEMM using
// mma.sync.m16n8k16 fp16 (fp32 accum).
//
// R13: CTA split into two decoupled 128-thread half-pipelines (n-halves).
//      Each half owns a private A copy (8KB) + its 64-column B half (4KB)
//      per stage, fills only what it reads, and syncs with a named barrier
//      (bar.sync g+1, 128). Halves overlap each other's barrier bubbles.
//      4 stages, distance-3 prefetch, cp_wait<2> (R9 schedule).

namespace {
constexpr int HH = 56, WW = 56, HW = 3136;
constexpr int CIN = 128, COUT = 256, BATCH = 32;
constexpr int KDIM = CIN * 9;           // 1152
constexpr int NDIM = BATCH * HW;        // 100352
constexpr int TM = 128, TN = 128, KT = 32;
constexpr int NKT = KDIM / KT;          // 36

constexpr int PW = 58;                  // padded H/W
constexpr uint32_t A_TILE_BYTES = TM * KT * 2;            // 8192 (per half copy)
constexpr uint32_t B_HALF_BYTES = 64 * KT * 2;            // 4096
constexpr uint32_t HALF_BYTES   = A_TILE_BYTES + B_HALF_BYTES;   // 12288
constexpr uint32_t STAGE_BYTES  = 2 * HALF_BYTES;         // 24576
constexpr uint32_t SMEM_TOTAL   = 4 * STAGE_BYTES;        // 98304
}

__device__ __half g_xh[(size_t)BATCH * PW * PW * CIN];        // padded CL fp16
__device__ __half g_wh[(size_t)NKT * 2 * TM * KT];            // smem-layout blobs

// ---------------- helpers ----------------
__device__ __forceinline__ uint32_t smem_u32(const void* p) {
    uint32_t a;
    asm("{ .reg .u64 t; cvta.to.shared.u64 t, %1; cvt.u32.u64 %0, t; }" : "=r"(a) : "l"(p));
    return a;
}
__device__ __forceinline__ void cp16(uint32_t dst, const void* src) {
    asm volatile("cp.async.cg.shared.global [%0], [%1], 16;"
                 :: "r"(dst), "l"(src) : "memory");
}
__device__ __forceinline__ void cp_commit() {
    asm volatile("cp.async.commit_group;" ::: "memory");
}
template <int N>
__device__ __forceinline__ void cp_wait() {
    asm volatile("cp.async.wait_group %0;" :: "n"(N) : "memory");
}
__device__ __forceinline__ void bar_sync(int id, int nthreads) {
    asm volatile("bar.sync %0, %1;" :: "r"(id), "r"(nthreads) : "memory");
}
__device__ __forceinline__ void ldsm4(uint32_t* r, uint32_t addr) {
    asm volatile("ldmatrix.sync.aligned.m8n8.x4.shared.b16 {%0,%1,%2,%3}, [%4];"
                 : "=r"(r[0]), "=r"(r[1]), "=r"(r[2]), "=r"(r[3]) : "r"(addr));
}
__device__ __forceinline__ void mma_f16(float* d, const uint32_t* a, const uint32_t* b) {
    asm volatile(
        "mma.sync.aligned.m16n8k16.row.col.f32.f16.f16.f32 "
        "{%0,%1,%2,%3}, {%4,%5,%6,%7}, {%8,%9}, {%0,%1,%2,%3};"
        : "+f"(d[0]), "+f"(d[1]), "+f"(d[2]), "+f"(d[3])
        : "r"(a[0]), "r"(a[1]), "r"(a[2]), "r"(a[3]), "r"(b[0]), "r"(b[1]));
}

// ---------------- pre-pass kernels ----------------
__global__ void xpose_kernel(const float* __restrict__ x) {
    __shared__ float tile[CIN][WW + 1];
    const int ih = blockIdx.x;
    const int b  = blockIdx.y;
    const int t  = threadIdx.x;
    const float* src = x + ((size_t)b * CIN * HH + ih) * WW;
#pragma unroll
    for (int it = 0; it < CIN * WW / 256; ++it) {
        int flat = it * 256 + t;
        int ci = flat / WW, iw = flat - ci * WW;
        tile[ci][iw] = src[(size_t)ci * HW + iw];
    }
    __syncthreads();
    __half* dst = g_xh + (((size_t)b * PW + (ih + 1)) * PW) * CIN;
#pragma unroll
    for (int it = 0; it < PW * CIN / 256; ++it) {
        int flat = it * 256 + t;
        int iw_p = flat >> 7, ci = flat & 127;
        float v = (iw_p == 0 || iw_p == PW - 1) ? 0.0f : tile[ci][iw_p - 1];
        dst[(size_t)iw_p * CIN + ci] = __float2half_rn(v);
    }
}

__global__ void border_kernel() {
    int id = blockIdx.x * blockDim.x + threadIdx.x;
    if (id >= BATCH * 2 * PW) return;
    int b = id / (2 * PW);
    int r = id - b * (2 * PW);
    int ih = (r < PW) ? 0 : (PW - 1);
    int iw = (r < PW) ? r : (r - PW);
    float4* p = reinterpret_cast<float4*>(
        g_xh + (((size_t)b * PW + ih) * PW + iw) * CIN);
#pragma unroll
    for (int q = 0; q < CIN * 2 / 16; ++q) p[q] = make_float4(0.f, 0.f, 0.f, 0.f);
}

__global__ void repack_w_kernel(const float* __restrict__ w) {
    int id = blockIdx.x * blockDim.x + threadIdx.x;
    int off  = id & 4095;
    int tile = id >> 12;
    int bm = tile & 1, kt = tile >> 1;
    int group = off >> 3, e = off & 7;
    int pair = group >> 3, sub = group & 7;
    int hco = sub >> 2, gs = sub & 3;
    int g = gs ^ (pair & 3);
    int co = bm * TM + pair * 2 + hco;
    int k_l = g * 8 + e;
    int p  = kt >> 2;
    int ci = ((kt & 3) << 5) + k_l;
    g_wh[id] = __float2half_rn(w[(size_t)co * KDIM + ci * 9 + p]);
}

// ---------------- main kernel ----------------
__global__ __launch_bounds__(256, 2)
void conv_mma_kernel(const float* __restrict__ bias, float* __restrict__ out)
{
    extern __shared__ char smc[];
    const uint32_t sbase = smem_u32(smc);

    const int tid  = threadIdx.x;
    const int lane = tid & 31;
    const int wid  = tid >> 5;
    const int bn   = blockIdx.x;
    const int bm   = blockIdx.y;

    const int g  = tid >> 7;          // n-half (0/1)
    const int tl = tid & 127;         // thread within half
    const uint32_t goff = (uint32_t)g * HALF_BYTES;

    // ---- fill assignments (within half) ----
    // A: 64B contiguous per thread (full 8KB A copy per half)
    const __half* a_src0 = g_wh + (size_t)bm * (TM * KT) + tl * 32;
    const uint32_t a_dst = goff + (uint32_t)tl * 64u;

    // B half: 64 n-columns, 2 threads per column
    const int b_n  = tl >> 1;                   // local n 0..63
    const int gsel = (tl & 1) * 2;
    const int nglob = bn * TN + g * 64 + b_n;
    const int bb  = nglob / HW;
    const int rem = nglob - bb * HW;
    const int oh  = rem / WW;
    const int ow  = rem - oh * WW;
    const __half* xb = g_xh + ((size_t)bb * PW + oh) * (PW * CIN) + (size_t)ow * CIN;
    const int pairB = b_n >> 1, halfB = b_n & 1;
    const uint32_t bg0 = (uint32_t)(pairB * 8 + halfB * 4 + (gsel       ^ (pairB & 3)));
    const uint32_t bg1 = (uint32_t)(pairB * 8 + halfB * 4 + ((gsel + 1) ^ (pairB & 3)));
    const uint32_t b_dst = goff + A_TILE_BYTES;

    auto fill = [&](int s, int kt) {
        const uint32_t soff = (uint32_t)s * STAGE_BYTES;
        const __half* asrc = a_src0 + (size_t)kt * (2 * TM * KT);
        cp16(sbase + soff + a_dst,      asrc);
        cp16(sbase + soff + a_dst + 16, asrc + 8);
        cp16(sbase + soff + a_dst + 32, asrc + 16);
        cp16(sbase + soff + a_dst + 48, asrc + 24);
        const int p  = kt >> 2;
        const int kh = (p * 11) >> 5;
        const int kw = p - 3 * kh;
        const int ci0 = ((kt & 3) << 5) + gsel * 8;
        const __half* bsrc = xb + ((size_t)kh * PW + kw) * CIN + ci0;
        const uint32_t bb0 = sbase + soff + b_dst;
        cp16(bb0 + bg0 * 16u, bsrc);
        cp16(bb0 + bg1 * 16u, bsrc + 8);
    };

    // ---- warp/lane compute coordinates ----
    const int wm = wid & 3;               // 4 warps per half cover M
    const int gr = lane >> 2, qc = lane & 3;
    const int mb = wm * 32;

    const int mrow = (lane & 7) + (((lane >> 3) & 1) << 3);
    const int matk = lane >> 4;
    uint32_t aoffbase[2], apx[2];
#pragma unroll
    for (int i = 0; i < 2; ++i) {
        int co_l = mb + i * 16 + mrow;
        int pa = co_l >> 1, ha = co_l & 1;
        aoffbase[i] = (uint32_t)(pa * 8 + ha * 4) * 16u;
        apx[i] = (uint32_t)(pa & 3);
    }

    const int rB = lane & 7;
    const uint32_t hB = (lane >> 3) & 1;
    const int qoct = lane >> 4;
    uint32_t bBase[4], bPx[4];
#pragma unroll
    for (int pj = 0; pj < 4; ++pj) {
        int j = 2 * pj + qoct;
        int n_l = j * 8 + rB;                 // local within half (0..63)
        int pb = n_l >> 1, hb = n_l & 1;
        bBase[pj] = (uint32_t)(pb * 8 + hb * 4) * 16u;
        bPx[pj] = (uint32_t)(pb & 3);
    }

    float acc[2][8][4];
#pragma unroll
    for (int i = 0; i < 2; ++i)
#pragma unroll
        for (int j = 0; j < 8; ++j)
#pragma unroll
            for (int q = 0; q < 4; ++q) acc[i][j][q] = 0.0f;

    // ---- prologue ----
    fill(0, 0); cp_commit();
    fill(1, 1); cp_commit();
    fill(2, 2); cp_commit();

    const int barid = g + 1;

#pragma unroll 4
    for (int kt = 0; kt < NKT; ++kt) {
        cp_wait<2>();
        bar_sync(barid, 128);      // half-local: data visible + prev compute done

        if (kt + 3 < NKT) fill((kt + 3) & 3, kt + 3);
        cp_commit();

        const uint32_t sA = sbase + (uint32_t)(kt & 3) * STAGE_BYTES + goff;
        const uint32_t sB = sA + A_TILE_BYTES;

#pragma unroll
        for (int ks = 0; ks < 2; ++ks) {
            uint32_t afr[2][4];
#pragma unroll
            for (int i = 0; i < 2; ++i) {
                uint32_t gg = (uint32_t)(ks * 2 + matk);
                ldsm4(afr[i], sA + aoffbase[i] + ((gg ^ apx[i]) << 4));
            }
            uint32_t bfr[4][4];
#pragma unroll
            for (int pj = 0; pj < 4; ++pj) {
                uint32_t gg = (uint32_t)(ks * 2) + hB;
                ldsm4(bfr[pj], sB + bBase[pj] + ((gg ^ bPx[pj]) << 4));
            }
#pragma unroll
            for (int i = 0; i < 2; ++i)
#pragma unroll
                for (int j = 0; j < 8; ++j)
                    mma_f16(acc[i][j], afr[i], &bfr[j >> 1][(j & 1) * 2]);
        }
    }

    // ---- epilogue: bias + float2 stores (registers only; no barrier) ----
#pragma unroll
    for (int i = 0; i < 2; ++i) {
        const int co0 = bm * TM + mb + i * 16 + gr;
        const int co1 = co0 + 8;
        const float bi0 = __ldg(&bias[co0]);
        const float bi1 = __ldg(&bias[co1]);
#pragma unroll
        for (int j = 0; j < 8; ++j) {
            const int n0 = bn * TN + g * 64 + j * 8 + 2 * qc;
            const int b2 = n0 / HW;
            const int r2 = n0 - b2 * HW;
            float* obase = out + (size_t)b2 * (COUT * HW) + r2;
            float2 v0 = make_float2(acc[i][j][0] + bi0, acc[i][j][1] + bi0);
            float2 v1 = make_float2(acc[i][j][2] + bi1, acc[i][j][3] + bi1);
            *reinterpret_cast<float2*>(obase + (size_t)co0 * HW) = v0;
            *reinterpret_cast<float2*>(obase + (size_t)co1 * HW) = v1;
        }
    }
}

extern "C" void kernel_launch(void* const* d_in, const int* in_sizes, int n_in,
                              void* d_out, int out_size) {
    const float* x    = (const float*)d_in[0];  // [32,128,56,56]
    const float* w    = (const float*)d_in[1];  // [256,128,3,3]
    const float* bias = (const float*)d_in[2];  // [256]
    float* out        = (float*)d_out;          // [32,256,56,56]

    border_kernel<<<(BATCH * 2 * PW + 255) / 256, 256>>>();
    {
        dim3 g(HH, BATCH);
        xpose_kernel<<<g, 256>>>(x);
    }
    repack_w_kernel<<<(NKT * 2 * TM * KT) / 256, 256>>>(w);

    cudaFuncSetAttribute(conv_mma_kernel, cudaFuncAttributeMaxDynamicSharedMemorySize,
                         (int)SMEM_TOTAL);
    dim3 grid(NDIM / TN, COUT / TM);  // (784, 2)
    conv_mma_kernel<<<grid, 256, SMEM_TOTAL>>>(bias, out);
}

// round 14
// speedup vs baseline: 1.3250x; 1.3250x over previous
#include <cuda_runtime.h>
#include <cuda_fp16.h>
#include <cstdint>

// Conv2d 3x3 (B=32,Cin=128,56x56 -> Cout=256, pad 1) as implicit GEMM using
// mma.sync.m16n8k16 fp16 (fp32 accum).
//
// R14 = R9 schedule (4 stages, one CTA-wide barrier per K-tile, cp_wait<2>,
// paired ldmatrix.x4) with:
//  - fill issued between the two ks half-steps (out of the post-barrier ramp)
//  - no pre-epilogue barrier
//  - border+repack fused into one pre-pass launch; xpose folds L/R border.

namespace {
constexpr int HH = 56, WW = 56, HW = 3136;
constexpr int CIN = 128, COUT = 256, BATCH = 32;
constexpr int KDIM = CIN * 9;           // 1152
constexpr int NDIM = BATCH * HW;        // 100352
constexpr int TM = 128, TN = 128, KT = 32;
constexpr int NKT = KDIM / KT;          // 36

constexpr int PW = 58;                  // padded H/W
constexpr uint32_t A_TILE_BYTES = TM * KT * 2;          // 8192
constexpr uint32_t B_TILE_BYTES = TN * KT * 2;          // 8192
constexpr uint32_t STAGE_BYTES  = A_TILE_BYTES + B_TILE_BYTES;  // 16384
constexpr uint32_t SMEM_TOTAL   = 4 * STAGE_BYTES;              // 65536
}

__device__ __half g_xh[(size_t)BATCH * PW * PW * CIN];        // padded CL fp16
__device__ __half g_wh[(size_t)NKT * 2 * TM * KT];            // smem-layout blobs

// ---------------- helpers ----------------
__device__ __forceinline__ uint32_t smem_u32(const void* p) {
    uint32_t a;
    asm("{ .reg .u64 t; cvta.to.shared.u64 t, %1; cvt.u32.u64 %0, t; }" : "=r"(a) : "l"(p));
    return a;
}
__device__ __forceinline__ void cp16(uint32_t dst, const void* src) {
    asm volatile("cp.async.cg.shared.global [%0], [%1], 16;"
                 :: "r"(dst), "l"(src) : "memory");
}
__device__ __forceinline__ void cp_commit() {
    asm volatile("cp.async.commit_group;" ::: "memory");
}
template <int N>
__device__ __forceinline__ void cp_wait() {
    asm volatile("cp.async.wait_group %0;" :: "n"(N) : "memory");
}
__device__ __forceinline__ void ldsm4(uint32_t* r, uint32_t addr) {
    asm volatile("ldmatrix.sync.aligned.m8n8.x4.shared.b16 {%0,%1,%2,%3}, [%4];"
                 : "=r"(r[0]), "=r"(r[1]), "=r"(r[2]), "=r"(r[3]) : "r"(addr));
}
__device__ __forceinline__ void mma_f16(float* d, const uint32_t* a, const uint32_t* b) {
    asm volatile(
        "mma.sync.aligned.m16n8k16.row.col.f32.f16.f16.f32 "
        "{%0,%1,%2,%3}, {%4,%5,%6,%7}, {%8,%9}, {%0,%1,%2,%3};"
        : "+f"(d[0]), "+f"(d[1]), "+f"(d[2]), "+f"(d[3])
        : "r"(a[0]), "r"(a[1]), "r"(a[2]), "r"(a[3]), "r"(b[0]), "r"(b[1]));
}

// ---------------- pre-pass kernels ----------------
// NCHW fp32 -> padded channels-last fp16; zeroes L/R border columns inline.
__global__ void xpose_kernel(const float* __restrict__ x) {
    __shared__ float tile[CIN][WW + 1];
    const int ih = blockIdx.x;
    const int b  = blockIdx.y;
    const int t  = threadIdx.x;
    const float* src = x + ((size_t)b * CIN * HH + ih) * WW;
#pragma unroll
    for (int it = 0; it < CIN * WW / 256; ++it) {
        int flat = it * 256 + t;
        int ci = flat / WW, iw = flat - ci * WW;
        tile[ci][iw] = src[(size_t)ci * HW + iw];
    }
    __syncthreads();
    __half* dst = g_xh + (((size_t)b * PW + (ih + 1)) * PW) * CIN;
#pragma unroll
    for (int it = 0; it < PW * CIN / 256; ++it) {
        int flat = it * 256 + t;
        int iw_p = flat >> 7, ci = flat & 127;
        float v = (iw_p == 0 || iw_p == PW - 1) ? 0.0f : tile[ci][iw_p - 1];
        dst[(size_t)iw_p * CIN + ci] = __float2half_rn(v);
    }
}

// Fused: weight repack (blocks 0..1151) + top/bottom border zero (rest).
__global__ void prep_kernel(const float* __restrict__ w) {
    const int REPACK_BLOCKS = (NKT * 2 * TM * KT) / 256;   // 1152
    if (blockIdx.x < REPACK_BLOCKS) {
        int id = blockIdx.x * 256 + threadIdx.x;
        int off  = id & 4095;
        int tile = id >> 12;
        int bm = tile & 1, kt = tile >> 1;
        int group = off >> 3, e = off & 7;
        int pair = group >> 3, sub = group & 7;
        int hco = sub >> 2, gs = sub & 3;
        int g = gs ^ (pair & 3);
        int co = bm * TM + pair * 2 + hco;
        int k_l = g * 8 + e;
        int p  = kt >> 2;
        int ci = ((kt & 3) << 5) + k_l;
        g_wh[id] = __float2half_rn(w[(size_t)co * KDIM + ci * 9 + p]);
    } else {
        int id = (blockIdx.x - REPACK_BLOCKS) * 256 + threadIdx.x;
        if (id >= BATCH * 2 * PW) return;
        int b = id / (2 * PW);
        int r = id - b * (2 * PW);
        int ih = (r < PW) ? 0 : (PW - 1);
        int iw = (r < PW) ? r : (r - PW);
        float4* p4 = reinterpret_cast<float4*>(
            g_xh + (((size_t)b * PW + ih) * PW + iw) * CIN);
#pragma unroll
        for (int q = 0; q < CIN * 2 / 16; ++q) p4[q] = make_float4(0.f, 0.f, 0.f, 0.f);
    }
}

// ---------------- main kernel ----------------
__global__ __launch_bounds__(256, 2)
void conv_mma_kernel(const float* __restrict__ bias, float* __restrict__ out)
{
    extern __shared__ char smc[];
    const uint32_t sbase = smem_u32(smc);

    const int tid  = threadIdx.x;
    const int lane = tid & 31;
    const int wid  = tid >> 5;
    const int bn   = blockIdx.x;
    const int bm   = blockIdx.y;

    // ---- fill assignments ----
    const __half* a_src0 = g_wh + (size_t)bm * (TM * KT) + tid * 16;
    const uint32_t a_dst = (uint32_t)tid * 32u;

    const int b_n  = tid >> 1;
    const int gsel = (tid & 1) * 2;
    const int nglob = bn * TN + b_n;
    const int bb  = nglob / HW;
    const int rem = nglob - bb * HW;
    const int oh  = rem / WW;
    const int ow  = rem - oh * WW;
    const __half* xb = g_xh + ((size_t)bb * PW + oh) * (PW * CIN) + (size_t)ow * CIN;
    const int pairB = b_n >> 1, halfB = b_n & 1;
    const uint32_t bg0 = (uint32_t)(pairB * 8 + halfB * 4 + (gsel       ^ (pairB & 3)));
    const uint32_t bg1 = (uint32_t)(pairB * 8 + halfB * 4 + ((gsel + 1) ^ (pairB & 3)));

    auto fill = [&](int s, int kt) {
        const uint32_t soff = (uint32_t)s * STAGE_BYTES;
        const __half* asrc = a_src0 + (size_t)kt * (2 * TM * KT);
        cp16(sbase + soff + a_dst,       asrc);
        cp16(sbase + soff + a_dst + 16,  asrc + 8);
        const int p  = kt >> 2;
        const int kh = (p * 11) >> 5;
        const int kw = p - 3 * kh;
        const int ci0 = ((kt & 3) << 5) + gsel * 8;
        const __half* bsrc = xb + ((size_t)kh * PW + kw) * CIN + ci0;
        const uint32_t bb0 = sbase + soff + A_TILE_BYTES;
        cp16(bb0 + bg0 * 16u, bsrc);
        cp16(bb0 + bg1 * 16u, bsrc + 8);
    };

    // ---- warp/lane compute coordinates ----
    const int wm = wid >> 1, wn = wid & 1;
    const int gr = lane >> 2, qc = lane & 3;
    const int mb = wm * 32, nb = wn * 64;

    const int mrow = (lane & 7) + (((lane >> 3) & 1) << 3);
    const int matk = lane >> 4;
    uint32_t aoffbase[2], apx[2];
#pragma unroll
    for (int i = 0; i < 2; ++i) {
        int co_l = mb + i * 16 + mrow;
        int pa = co_l >> 1, ha = co_l & 1;
        aoffbase[i] = (uint32_t)(pa * 8 + ha * 4) * 16u;
        apx[i] = (uint32_t)(pa & 3);
    }

    const int rB = lane & 7;
    const uint32_t hB = (lane >> 3) & 1;
    const int qoct = lane >> 4;
    uint32_t bBase[4], bPx[4];
#pragma unroll
    for (int pj = 0; pj < 4; ++pj) {
        int j = 2 * pj + qoct;
        int n_l = nb + j * 8 + rB;
        int pb = n_l >> 1, hb = n_l & 1;
        bBase[pj] = (uint32_t)(pb * 8 + hb * 4) * 16u;
        bPx[pj] = (uint32_t)(pb & 3);
    }

    float acc[2][8][4];
#pragma unroll
    for (int i = 0; i < 2; ++i)
#pragma unroll
        for (int j = 0; j < 8; ++j)
#pragma unroll
            for (int q = 0; q < 4; ++q) acc[i][j][q] = 0.0f;

    // ---- pipeline prologue (depth 3 of 4 stages) ----
    fill(0, 0); cp_commit();
    fill(1, 1); cp_commit();
    fill(2, 2); cp_commit();

#pragma unroll 4
    for (int kt = 0; kt < NKT; ++kt) {
        cp_wait<2>();
        __syncthreads();   // stage kt visible + prev compute done

        const uint32_t sA = sbase + (uint32_t)(kt & 3) * STAGE_BYTES;
        const uint32_t sB = sA + A_TILE_BYTES;

#pragma unroll
        for (int ks = 0; ks < 2; ++ks) {
            uint32_t afr[2][4];
#pragma unroll
            for (int i = 0; i < 2; ++i) {
                uint32_t g = (uint32_t)(ks * 2 + matk);
                ldsm4(afr[i], sA + aoffbase[i] + ((g ^ apx[i]) << 4));
            }
            uint32_t bfr[4][4];
#pragma unroll
            for (int pj = 0; pj < 4; ++pj) {
                uint32_t g = (uint32_t)(ks * 2) + hB;
                ldsm4(bfr[pj], sB + bBase[pj] + ((g ^ bPx[pj]) << 4));
            }
#pragma unroll
            for (int i = 0; i < 2; ++i)
#pragma unroll
                for (int j = 0; j < 8; ++j)
                    mma_f16(acc[i][j], afr[i], &bfr[j >> 1][(j & 1) * 2]);

            // issue next-stage fill while ks=0 MMAs drain (out of the ramp)
            if (ks == 0) {
                if (kt + 3 < NKT) fill((kt + 3) & 3, kt + 3);
                cp_commit();
            }
        }
    }

    // ---- epilogue: bias + float2 stores (registers only; no barrier) ----
#pragma unroll
    for (int i = 0; i < 2; ++i) {
        const int co0 = bm * TM + mb + i * 16 + gr;
        const int co1 = co0 + 8;
        const float bi0 = __ldg(&bias[co0]);
        const float bi1 = __ldg(&bias[co1]);
#pragma unroll
        for (int j = 0; j < 8; ++j) {
            const int n0 = bn * TN + nb + j * 8 + 2 * qc;
            const int b2 = n0 / HW;
            const int r2 = n0 - b2 * HW;
            float* obase = out + (size_t)b2 * (COUT * HW) + r2;
            float2 v0 = make_float2(acc[i][j][0] + bi0, acc[i][j][1] + bi0);
            float2 v1 = make_float2(acc[i][j][2] + bi1, acc[i][j][3] + bi1);
            *reinterpret_cast<float2*>(obase + (size_t)co0 * HW) = v0;
            *reinterpret_cast<float2*>(obase + (size_t)co1 * HW) = v1;
        }
    }
}

extern "C" void kernel_launch(void* const* d_in, const int* in_sizes, int n_in,
                              void* d_out, int out_size) {
    const float* x    = (const float*)d_in[0];  // [32,128,56,56]
    const float* w    = (const float*)d_in[1];  // [256,128,3,3]
    const float* bias = (const float*)d_in[2];  // [256]
    float* out        = (float*)d_out;          // [32,256,56,56]

    const int REPACK_BLOCKS = (NKT * 2 * TM * KT) / 256;            // 1152
    const int BORDER_BLOCKS = (BATCH * 2 * PW + 255) / 256;         // 15
    prep_kernel<<<REPACK_BLOCKS + BORDER_BLOCKS, 256>>>(w);
    {
        dim3 g(HH, BATCH);
        xpose_kernel<<<g, 256>>>(x);
    }

    cudaFuncSetAttribute(conv_mma_kernel, cudaFuncAttributeMaxDynamicSharedMemorySize,
                         (int)SMEM_TOTAL);
    dim3 grid(NDIM / TN, COUT / TM);  // (784, 2)
    conv_mma_kernel<<<grid, 256, SMEM_TOTAL>>>(bias, out);
}